// round 1
// baseline (speedup 1.0000x reference)
#include <cuda_runtime.h>
#include <math.h>

namespace {

constexpr int B  = 256;
constexpr int L  = 128;
constexpr int H  = 512;
constexpr int H4 = 2048;

// ---------------- device state (scratch; allocation-free per rules) ----------------
__device__ float g_h[2][B * H];                 // LSTM hidden, double buffered by step parity
__device__ float g_c[B * H];                    // LSTM cell (elementwise-owned, single buffer)
__device__ float g_enc_out[(size_t)B * L * H];  // [b][l][h]
__device__ float g_enc_w1[(size_t)B * L * H];   // enc_out @ w1^T, [b][l][h]
__device__ float g_q[B * H];                    // h @ w2^T per decoder step
__device__ float g_ctx[B * H];                  // attention context
__device__ float g_dec_in[2][B];                // decoder scalar input, double buffered
__device__ float g_dwi_main[H4 * H];            // dec_Wi[:, 0:512] repacked (aligned rows)
__device__ float g_dwi_last[H4];                // dec_Wi[:, 512]

// ---------------- math helpers ----------------
__device__ __forceinline__ float sigmoid_acc(float x) {
    return 1.0f / (1.0f + __expf(-x));
}
__device__ __forceinline__ float tanh_acc(float x) {
    float e = __expf(-2.0f * fabsf(x));
    float r = (1.0f - e) / (1.0f + e);
    return copysignf(r, x);
}
__device__ __forceinline__ float tanh_fast(float x) {
    float y;
    asm("tanh.approx.f32 %0, %1;" : "=f"(y) : "f"(x));
    return y;
}

// ---------------- init ----------------
__global__ void k_init() {
    int i = blockIdx.x * blockDim.x + threadIdx.x;
    int stride = gridDim.x * blockDim.x;
    for (int j = i; j < B * H; j += stride) {
        g_h[0][j] = 0.0f;
        g_c[j]    = 0.0f;
    }
    if (i < B) g_dec_in[0][i] = 0.0f;
}

// ---------------- one-time repack of dec_Wi [2048 x 513] ----------------
__global__ void k_repack(const float* __restrict__ dwi) {
    int i = blockIdx.x * blockDim.x + threadIdx.x;
    int stride = gridDim.x * blockDim.x;
    for (int j = i; j < H4 * H; j += stride) {
        int n = j >> 9;          // /512
        int k = j & (H - 1);     // %512
        g_dwi_main[j] = dwi[n * (H + 1) + k];
    }
    if (i < H4) g_dwi_last[i] = dwi[i * (H + 1) + H];
}

// ---------------- fused LSTM step (GEMM + gates) ----------------
// Block tile: 32 b x 32 h, all 4 gates. grid = (H/32=16, B/32=8), 256 threads.
// ENC: z = x_t*enc_Wi + h@Wh^T + b           (K = 512)
// DEC: z = [ctx,dec_in]@dec_Wi^T + h@Wh^T + b (K = 512 + 512 + scalar)
template <bool DEC>
__global__ void __launch_bounds__(256) k_lstm(
    const float* __restrict__ Wh,     // [2048 x 512]
    const float* __restrict__ WiVec,  // enc: enc_Wi [2048]; dec: unused
    const float* __restrict__ bias,   // [2048]
    const int*   __restrict__ xs,     // [B x L]
    const int*   __restrict__ argsort,// [B x L] (dec only)
    int t)
{
    __shared__ float As[32][36];      // [b_local][k] (pad 36 keeps float4 stores aligned)
    __shared__ float Bs[32][4][32];   // [k][gate][h_local]

    const int tid = threadIdx.x;
    const int tx  = tid & 31;         // h_local
    const int ty  = tid >> 5;         // 0..7 -> 4 b's each
    const int h0  = blockIdx.x * 32;
    const int b0  = blockIdx.y * 32;
    const int p   = t & 1;

    const int bl = tid >> 3;          // 0..31 (A-load row)
    const int kl = (tid & 7) * 4;     // 0..28 (A-load k quad)

    float acc[4][4] = {};             // [r(b)][g]

    const int NT = DEC ? 32 : 16;
    for (int kt = 0; kt < NT; kt++) {
        const bool ph0 = DEC && (kt < 16);
        const float* IN = ph0 ? g_ctx : g_h[p];
        const float* W  = ph0 ? g_dwi_main : Wh;
        const int k0 = (kt & 15) * 32;

        __syncthreads();
        {
            float4 av = *(const float4*)&IN[(b0 + bl) * H + k0 + kl];
            *(float4*)&As[bl][kl] = av;
        }
        {
            const int kq = ty * 4;
#pragma unroll
            for (int g = 0; g < 4; g++) {
                float4 wv = *(const float4*)&W[(g * H + h0 + tx) * H + k0 + kq];
                Bs[kq + 0][g][tx] = wv.x;
                Bs[kq + 1][g][tx] = wv.y;
                Bs[kq + 2][g][tx] = wv.z;
                Bs[kq + 3][g][tx] = wv.w;
            }
        }
        __syncthreads();

#pragma unroll
        for (int k = 0; k < 32; k++) {
            float a0 = As[ty * 4 + 0][k];
            float a1 = As[ty * 4 + 1][k];
            float a2 = As[ty * 4 + 2][k];
            float a3 = As[ty * 4 + 3][k];
            float w0 = Bs[k][0][tx];
            float w1v = Bs[k][1][tx];
            float w2v = Bs[k][2][tx];
            float w3v = Bs[k][3][tx];
            acc[0][0] += a0 * w0;  acc[0][1] += a0 * w1v;  acc[0][2] += a0 * w2v;  acc[0][3] += a0 * w3v;
            acc[1][0] += a1 * w0;  acc[1][1] += a1 * w1v;  acc[1][2] += a1 * w2v;  acc[1][3] += a1 * w3v;
            acc[2][0] += a2 * w0;  acc[2][1] += a2 * w1v;  acc[2][2] += a2 * w2v;  acc[2][3] += a2 * w3v;
            acc[3][0] += a3 * w0;  acc[3][1] += a3 * w1v;  acc[3][2] += a3 * w2v;  acc[3][3] += a3 * w3v;
        }
    }

    // epilogue: gates
    const int h = h0 + tx;
    float bv[4], wiv[4];
#pragma unroll
    for (int g = 0; g < 4; g++) {
        bv[g]  = bias[g * H + h];
        wiv[g] = DEC ? g_dwi_last[g * H + h] : WiVec[g * H + h];
    }
#pragma unroll
    for (int r = 0; r < 4; r++) {
        const int b = b0 + ty * 4 + r;
        const float xb = DEC ? g_dec_in[p][b] : (float)xs[b * L + t];
        const float zi = acc[r][0] + bv[0] + xb * wiv[0];
        const float zf = acc[r][1] + bv[1] + xb * wiv[1];
        const float zg = acc[r][2] + bv[2] + xb * wiv[2];
        const float zo = acc[r][3] + bv[3] + xb * wiv[3];
        const float c  = sigmoid_acc(zf) * g_c[b * H + h] + sigmoid_acc(zi) * tanh_acc(zg);
        const float hn = sigmoid_acc(zo) * tanh_acc(c);
        g_c[b * H + h] = c;
        g_h[p ^ 1][b * H + h] = hn;
        if (!DEC) g_enc_out[((size_t)b * L + t) * H + h] = hn;
    }

    // teacher-forced next decoder input (write to the OTHER buffer; no race)
    if (DEC && blockIdx.x == 0 && tx == 0) {
#pragma unroll
        for (int r = 0; r < 4; r++) {
            const int b = b0 + ty * 4 + r;
            const int idx = argsort[b * L + t];
            g_dec_in[p ^ 1][b] = (float)xs[b * L + idx];
        }
    }
}

// ---------------- enc_w1 = enc_out @ w1^T  (M=B*L=32768, N=512, K=512) ----------------
// 64x64 tile, 4x4 micro, KT=16. grid = (8, 512), 256 threads.
__global__ void __launch_bounds__(256) k_encw1(const float* __restrict__ w1) {
    __shared__ float As[16][68];
    __shared__ float Bs[16][68];

    const int tid = threadIdx.x;
    const int tx = tid & 15;     // n quad
    const int ty = tid >> 4;     // m quad
    const int n0 = blockIdx.x * 64;
    const int m0 = blockIdx.y * 64;

    const int rl = tid >> 2;           // 0..63
    const int kl = (tid & 3) * 4;      // 0,4,8,12

    float acc[4][4] = {};

    for (int k0 = 0; k0 < H; k0 += 16) {
        __syncthreads();
        {
            float4 av = *(const float4*)&g_enc_out[(size_t)(m0 + rl) * H + k0 + kl];
            As[kl + 0][rl] = av.x; As[kl + 1][rl] = av.y;
            As[kl + 2][rl] = av.z; As[kl + 3][rl] = av.w;
            float4 bv = *(const float4*)&w1[(n0 + rl) * H + k0 + kl];
            Bs[kl + 0][rl] = bv.x; Bs[kl + 1][rl] = bv.y;
            Bs[kl + 2][rl] = bv.z; Bs[kl + 3][rl] = bv.w;
        }
        __syncthreads();
#pragma unroll
        for (int k = 0; k < 16; k++) {
            float4 a = *(const float4*)&As[k][ty * 4];
            float4 w = *(const float4*)&Bs[k][tx * 4];
            acc[0][0] += a.x * w.x; acc[0][1] += a.x * w.y; acc[0][2] += a.x * w.z; acc[0][3] += a.x * w.w;
            acc[1][0] += a.y * w.x; acc[1][1] += a.y * w.y; acc[1][2] += a.y * w.z; acc[1][3] += a.y * w.w;
            acc[2][0] += a.z * w.x; acc[2][1] += a.z * w.y; acc[2][2] += a.z * w.z; acc[2][3] += a.z * w.w;
            acc[3][0] += a.w * w.x; acc[3][1] += a.w * w.y; acc[3][2] += a.w * w.z; acc[3][3] += a.w * w.w;
        }
    }
#pragma unroll
    for (int i = 0; i < 4; i++) {
        float4 o = make_float4(acc[i][0], acc[i][1], acc[i][2], acc[i][3]);
        *(float4*)&g_enc_w1[(size_t)(m0 + ty * 4 + i) * H + n0 + tx * 4] = o;
    }
}

// ---------------- q = h @ w2^T  (M=256, N=512, K=512) ----------------
// 32x32 tile, 2x2 micro, KT=32. grid = (16, 8), 256 threads.
__global__ void __launch_bounds__(256) k_qproj(const float* __restrict__ w2, int t) {
    __shared__ float As[32][34];
    __shared__ float Bs[32][34];

    const int tid = threadIdx.x;
    const int tx = tid & 15;    // n pair
    const int ty = tid >> 4;    // m pair
    const int n0 = blockIdx.x * 32;
    const int m0 = blockIdx.y * 32;
    const float* A = g_h[t & 1];

    const int rl = tid >> 3;          // 0..31
    const int kl = (tid & 7) * 4;     // 0..28

    float a00 = 0.f, a01 = 0.f, a10 = 0.f, a11 = 0.f;

    for (int k0 = 0; k0 < H; k0 += 32) {
        __syncthreads();
        {
            float4 av = *(const float4*)&A[(m0 + rl) * H + k0 + kl];
            As[kl + 0][rl] = av.x; As[kl + 1][rl] = av.y;
            As[kl + 2][rl] = av.z; As[kl + 3][rl] = av.w;
            float4 bv = *(const float4*)&w2[(n0 + rl) * H + k0 + kl];
            Bs[kl + 0][rl] = bv.x; Bs[kl + 1][rl] = bv.y;
            Bs[kl + 2][rl] = bv.z; Bs[kl + 3][rl] = bv.w;
        }
        __syncthreads();
#pragma unroll
        for (int k = 0; k < 32; k++) {
            float2 a = *(const float2*)&As[k][ty * 2];
            float2 w = *(const float2*)&Bs[k][tx * 2];
            a00 += a.x * w.x; a01 += a.x * w.y;
            a10 += a.y * w.x; a11 += a.y * w.y;
        }
    }
    const int m = m0 + ty * 2;
    const int n = n0 + tx * 2;
    g_q[m * H + n]           = a00;
    g_q[m * H + n + 1]       = a01;
    g_q[(m + 1) * H + n]     = a10;
    g_q[(m + 1) * H + n + 1] = a11;
}

// ---------------- attention + softmax + log_softmax output + context ----------------
// One block per batch element b. 256 threads.
__global__ void __launch_bounds__(256) k_attn(const float* __restrict__ vt,
                                              float* __restrict__ out, int t) {
    __shared__ float q_s[H];
    __shared__ float vt_s[H];
    __shared__ float sc[L];
    __shared__ float aj[L];

    const int b = blockIdx.x;
    const int tid = threadIdx.x;
    const int lane = tid & 31;
    const int w = tid >> 5;

    for (int i = tid; i < H; i += 256) {
        q_s[i]  = g_q[b * H + i];
        vt_s[i] = vt[i];
    }
    __syncthreads();

    // scores[l] = sum_h vt[h] * tanh(enc_w1[b,l,h] + q[h]); warp w handles 16 l's
#pragma unroll 1
    for (int li = 0; li < 16; li++) {
        const int l = w * 16 + li;
        const float4* e4 = (const float4*)(g_enc_w1 + (size_t)(b * L + l) * H);
        float s = 0.f;
#pragma unroll
        for (int j = 0; j < 4; j++) {
            float4 e  = e4[lane + j * 32];
            float4 qv = *(const float4*)&q_s[(lane + j * 32) * 4];
            float4 vv = *(const float4*)&vt_s[(lane + j * 32) * 4];
            s += vv.x * tanh_fast(e.x + qv.x);
            s += vv.y * tanh_fast(e.y + qv.y);
            s += vv.z * tanh_fast(e.z + qv.z);
            s += vv.w * tanh_fast(e.w + qv.w);
        }
#pragma unroll
        for (int o = 16; o > 0; o >>= 1) s += __shfl_xor_sync(0xffffffffu, s, o);
        if (lane == 0) sc[l] = s;
    }
    __syncthreads();

    // softmax + log_softmax by warp 0 (4 l's per lane)
    if (w == 0) {
        float sv[4];
        float m = -1e30f;
#pragma unroll
        for (int k = 0; k < 4; k++) { sv[k] = sc[lane * 4 + k]; m = fmaxf(m, sv[k]); }
#pragma unroll
        for (int o = 16; o > 0; o >>= 1) m = fmaxf(m, __shfl_xor_sync(0xffffffffu, m, o));
        float e[4], sum = 0.f;
#pragma unroll
        for (int k = 0; k < 4; k++) { e[k] = __expf(sv[k] - m); sum += e[k]; }
#pragma unroll
        for (int o = 16; o > 0; o >>= 1) sum += __shfl_xor_sync(0xffffffffu, sum, o);
        const float ls  = __logf(sum);
        const float inv = 1.0f / sum;
        float* orow = out + ((size_t)b * L + t) * L;
#pragma unroll
        for (int k = 0; k < 4; k++) {
            orow[lane * 4 + k] = sv[k] - m - ls;
            aj[lane * 4 + k]   = e[k] * inv;
        }
    }
    __syncthreads();

    // context[h] = sum_l aj[l] * enc_out[b,l,h]; 256 threads x 2 h's
    const int h2 = tid * 2;
    float ax = 0.f, ay = 0.f;
    const float* base = g_enc_out + (size_t)b * L * H + h2;
#pragma unroll 4
    for (int l = 0; l < L; l++) {
        const float a = aj[l];
        const float2 v = *(const float2*)(base + (size_t)l * H);
        ax += a * v.x;
        ay += a * v.y;
    }
    g_ctx[b * H + h2]     = ax;
    g_ctx[b * H + h2 + 1] = ay;
}

}  // namespace

extern "C" void kernel_launch(void* const* d_in, const int* in_sizes, int n_in,
                              void* d_out, int out_size) {
    (void)in_sizes; (void)n_in; (void)out_size;
    const int*   xs      = (const int*)d_in[0];
    // d_in[1] = x_lens (unused by the math)
    const int*   argsort = (const int*)d_in[2];
    const float* enc_Wi  = (const float*)d_in[3];
    const float* enc_Wh  = (const float*)d_in[4];
    const float* enc_b   = (const float*)d_in[5];
    const float* dec_Wi  = (const float*)d_in[6];
    const float* dec_Wh  = (const float*)d_in[7];
    const float* dec_b   = (const float*)d_in[8];
    const float* w1      = (const float*)d_in[9];
    const float* w2      = (const float*)d_in[10];
    const float* vt      = (const float*)d_in[11];
    float* out = (float*)d_out;

    k_init<<<128, 256>>>();
    k_repack<<<256, 256>>>(dec_Wi);

    const dim3 lstm_grid(H / 32, B / 32);   // (16, 8)

    // ---- encoder: 128 sequential LSTM steps ----
    for (int t = 0; t < L; t++) {
        k_lstm<false><<<lstm_grid, 256>>>(enc_Wh, enc_Wi, enc_b, xs, nullptr, t);
    }

    // ---- hoisted projection enc_w1 = enc_out @ w1^T ----
    k_encw1<<<dim3(H / 64, (B * L) / 64), 256>>>(w1);   // (8, 512)

    // ---- decoder: 128 sequential steps of q-proj -> attention -> LSTM ----
    for (int t = 0; t < L; t++) {
        k_qproj<<<dim3(H / 32, B / 32), 256>>>(w2, t);  // (16, 8)
        k_attn<<<B, 256>>>(vt, out, t);
        k_lstm<true><<<lstm_grid, 256>>>(dec_Wh, nullptr, dec_b, xs, argsort, t);
    }
}

// round 2
// speedup vs baseline: 1.4171x; 1.4171x over previous
#include <cuda_runtime.h>
#include <math.h>

namespace {

constexpr int B  = 256;
constexpr int L  = 128;
constexpr int H  = 512;
constexpr int H4 = 2048;

// ---------------- device state (allocation-free scratch) ----------------
__device__ float g_h[2][B * H];                 // hidden, double buffered by parity
__device__ float g_c[B * H];                    // cell
__device__ float g_enc_out[(size_t)B * L * H];  // [b][l][h]
__device__ float g_enc_w1[(size_t)B * L * H];   // enc_out @ w1^T
__device__ float g_ctx[B * H];                  // attention context
__device__ float g_dec_in[2][B];                // decoder scalar input
__device__ float g_dwcat[H4 * 1024];            // [Wi_main | Wh] for decoder, row stride 1024
__device__ float g_dwi_last[H4];                // dec_Wi[:, 512]
__device__ float g_zpart[2 * B * H4];           // split-K partials for LSTM z
__device__ float g_qpart[8 * B * H];            // split-K partials for q = h @ w2^T

// ---------------- math helpers ----------------
__device__ __forceinline__ float sigmoid_acc(float x) {
    return 1.0f / (1.0f + __expf(-x));
}
__device__ __forceinline__ float tanh_acc(float x) {
    float e = __expf(-2.0f * fabsf(x));
    float r = (1.0f - e) / (1.0f + e);
    return copysignf(r, x);
}
__device__ __forceinline__ float tanh_fast(float x) {
    float y;
    asm("tanh.approx.f32 %0, %1;" : "=f"(y) : "f"(x));
    return y;
}

// ---------------- init ----------------
__global__ void k_init() {
    int i = blockIdx.x * blockDim.x + threadIdx.x;
    int stride = gridDim.x * blockDim.x;
    for (int j = i; j < B * H; j += stride) {
        g_h[0][j] = 0.0f;
        g_c[j]    = 0.0f;
    }
    if (i < B) g_dec_in[0][i] = 0.0f;
}

// ---------------- one-time repack: dec weights -> [Wi_main | Wh] [2048 x 1024] ----------------
__global__ void k_repack(const float* __restrict__ dwi, const float* __restrict__ dwh) {
    int i = blockIdx.x * blockDim.x + threadIdx.x;
    int stride = gridDim.x * blockDim.x;
    for (int j = i; j < H4 * 1024; j += stride) {
        int n = j >> 10;          // /1024
        int k = j & 1023;         // %1024
        g_dwcat[j] = (k < H) ? dwi[n * (H + 1) + k] : dwh[n * H + (k - H)];
    }
    if (i < H4) g_dwi_last[i] = dwi[i * (H + 1) + H];
}

// ---------------- generic split-K GEMM:  part[kz] = A @ W^T over K-chunk ----------------
// C is [256 x N], A rows have stride 512 (CONCAT: k<512 from A0=ctx, else A1=h).
// Tile 64x64, micro 4x4, BK=16, double-buffered smem, one sync per tile.
// grid = (N/64, 4, KS), 256 threads.
template <int KTOT, int KS, bool CONCAT>
__global__ void __launch_bounds__(256) k_gemm(
    const float* __restrict__ W,    // [N x KTOT]
    const float* __restrict__ A0,
    const float* __restrict__ A1,
    float* __restrict__ part)       // [KS][256][N]
{
    constexpr int KC = KTOT / KS;
    constexpr int NT = KC / 16;

    __shared__ float As[2][16][68];
    __shared__ float Bs[2][16][68];

    const int tid = threadIdx.x;
    const int tx  = tid & 15;           // n quad
    const int ty  = tid >> 4;           // m quad
    const int n0  = blockIdx.x * 64;
    const int m0  = blockIdx.y * 64;
    const int kbase = blockIdx.z * KC;
    const int N   = gridDim.x * 64;

    const int rl = tid >> 2;            // 0..63 (load row within tile)
    const int kl = (tid & 3) * 4;       // 0,4,8,12 (load k quad)

    float acc[4][4] = {};

    auto gload = [&](int k0, float4& av, float4& wv) {
        const int k = k0 + kl;
        const float* asrc;
        if (CONCAT) {
            asrc = (k < 512) ? (A0 + (m0 + rl) * 512 + k)
                             : (A1 + (m0 + rl) * 512 + (k - 512));
        } else {
            asrc = A0 + (m0 + rl) * 512 + k;
        }
        av = *(const float4*)asrc;
        wv = *(const float4*)&W[(size_t)(n0 + rl) * KTOT + k];
    };
    auto sstore = [&](int buf, float4 av, float4 wv) {
        As[buf][kl + 0][rl] = av.x; As[buf][kl + 1][rl] = av.y;
        As[buf][kl + 2][rl] = av.z; As[buf][kl + 3][rl] = av.w;
        Bs[buf][kl + 0][rl] = wv.x; Bs[buf][kl + 1][rl] = wv.y;
        Bs[buf][kl + 2][rl] = wv.z; Bs[buf][kl + 3][rl] = wv.w;
    };

    {
        float4 av, wv;
        gload(kbase, av, wv);
        sstore(0, av, wv);
    }
    __syncthreads();

    for (int t = 0; t < NT; t++) {
        float4 av, wv;
        const bool more = (t + 1 < NT);
        if (more) gload(kbase + (t + 1) * 16, av, wv);

        const int cb = t & 1;
#pragma unroll
        for (int k = 0; k < 16; k++) {
            float4 a = *(const float4*)&As[cb][k][ty * 4];
            float4 b = *(const float4*)&Bs[cb][k][tx * 4];
            acc[0][0] += a.x * b.x; acc[0][1] += a.x * b.y; acc[0][2] += a.x * b.z; acc[0][3] += a.x * b.w;
            acc[1][0] += a.y * b.x; acc[1][1] += a.y * b.y; acc[1][2] += a.y * b.z; acc[1][3] += a.y * b.w;
            acc[2][0] += a.z * b.x; acc[2][1] += a.z * b.y; acc[2][2] += a.z * b.z; acc[2][3] += a.z * b.w;
            acc[3][0] += a.w * b.x; acc[3][1] += a.w * b.y; acc[3][2] += a.w * b.z; acc[3][3] += a.w * b.w;
        }
        if (more) sstore(cb ^ 1, av, wv);  // writes the buffer NOT being read: no race
        __syncthreads();
    }

    float* dst = part + (size_t)blockIdx.z * 256 * N;
#pragma unroll
    for (int i = 0; i < 4; i++) {
        float4 o = make_float4(acc[i][0], acc[i][1], acc[i][2], acc[i][3]);
        *(float4*)&dst[(size_t)(m0 + ty * 4 + i) * N + n0 + tx * 4] = o;
    }
}

// ---------------- gates: reduce split-K partials, activations, state update ----------------
template <bool DEC>
__global__ void __launch_bounds__(256) k_gates(
    const float* __restrict__ bias,    // [2048]
    const float* __restrict__ wivec,   // scalar-input weights [2048]
    const int*   __restrict__ xs,
    const int*   __restrict__ argsort,
    int t)
{
    const int idx = blockIdx.x * 256 + threadIdx.x;
    const int b = idx >> 9;
    const int h = idx & (H - 1);
    const int p = t & 1;

    const float xb = DEC ? g_dec_in[p][b] : (float)xs[b * L + t];

    float z[4];
#pragma unroll
    for (int g = 0; g < 4; g++) {
        const int zn = g * H + h;
        float s = bias[zn] + xb * wivec[zn];
        s += g_zpart[(size_t)b * H4 + zn];
        s += g_zpart[(size_t)(B * H4) + (size_t)b * H4 + zn];
        z[g] = s;
    }
    const float c  = sigmoid_acc(z[1]) * g_c[idx] + sigmoid_acc(z[0]) * tanh_acc(z[2]);
    const float hn = sigmoid_acc(z[3]) * tanh_acc(c);
    g_c[idx] = c;
    g_h[p ^ 1][idx] = hn;
    if (!DEC) g_enc_out[((size_t)b * L + t) * H + h] = hn;
    if (DEC && h == 0) {
        g_dec_in[p ^ 1][b] = (float)xs[b * L + argsort[b * L + t]];
    }
}

// ---------------- enc_w1 = enc_out @ w1^T  (M=32768, N=512, K=512) ----------------
__global__ void __launch_bounds__(256) k_encw1(const float* __restrict__ w1) {
    __shared__ float As[16][68];
    __shared__ float Bs[16][68];

    const int tid = threadIdx.x;
    const int tx = tid & 15;
    const int ty = tid >> 4;
    const int n0 = blockIdx.x * 64;
    const int m0 = blockIdx.y * 64;

    const int rl = tid >> 2;
    const int kl = (tid & 3) * 4;

    float acc[4][4] = {};

    for (int k0 = 0; k0 < H; k0 += 16) {
        __syncthreads();
        {
            float4 av = *(const float4*)&g_enc_out[(size_t)(m0 + rl) * H + k0 + kl];
            As[kl + 0][rl] = av.x; As[kl + 1][rl] = av.y;
            As[kl + 2][rl] = av.z; As[kl + 3][rl] = av.w;
            float4 bv = *(const float4*)&w1[(n0 + rl) * H + k0 + kl];
            Bs[kl + 0][rl] = bv.x; Bs[kl + 1][rl] = bv.y;
            Bs[kl + 2][rl] = bv.z; Bs[kl + 3][rl] = bv.w;
        }
        __syncthreads();
#pragma unroll
        for (int k = 0; k < 16; k++) {
            float4 a = *(const float4*)&As[k][ty * 4];
            float4 w = *(const float4*)&Bs[k][tx * 4];
            acc[0][0] += a.x * w.x; acc[0][1] += a.x * w.y; acc[0][2] += a.x * w.z; acc[0][3] += a.x * w.w;
            acc[1][0] += a.y * w.x; acc[1][1] += a.y * w.y; acc[1][2] += a.y * w.z; acc[1][3] += a.y * w.w;
            acc[2][0] += a.z * w.x; acc[2][1] += a.z * w.y; acc[2][2] += a.z * w.z; acc[2][3] += a.z * w.w;
            acc[3][0] += a.w * w.x; acc[3][1] += a.w * w.y; acc[3][2] += a.w * w.z; acc[3][3] += a.w * w.w;
        }
    }
#pragma unroll
    for (int i = 0; i < 4; i++) {
        float4 o = make_float4(acc[i][0], acc[i][1], acc[i][2], acc[i][3]);
        *(float4*)&g_enc_w1[(size_t)(m0 + ty * 4 + i) * H + n0 + tx * 4] = o;
    }
}

// ---------------- attention: scores + softmax + log_softmax + context ----------------
__global__ void __launch_bounds__(256) k_attn(const float* __restrict__ vt,
                                              float* __restrict__ out, int t) {
    __shared__ float q_s[H];
    __shared__ float vt_s[H];
    __shared__ float sc[L];
    __shared__ float aj[L];

    const int b = blockIdx.x;
    const int tid = threadIdx.x;
    const int lane = tid & 31;
    const int w = tid >> 5;

    for (int i = tid; i < H; i += 256) {
        float s = 0.0f;
#pragma unroll
        for (int sp = 0; sp < 8; sp++)
            s += g_qpart[(size_t)sp * (B * H) + b * H + i];
        q_s[i]  = s;
        vt_s[i] = vt[i];
    }
    __syncthreads();

#pragma unroll 1
    for (int li = 0; li < 16; li++) {
        const int l = w * 16 + li;
        const float4* e4 = (const float4*)(g_enc_w1 + (size_t)(b * L + l) * H);
        float s = 0.f;
#pragma unroll
        for (int j = 0; j < 4; j++) {
            float4 e  = e4[lane + j * 32];
            float4 qv = *(const float4*)&q_s[(lane + j * 32) * 4];
            float4 vv = *(const float4*)&vt_s[(lane + j * 32) * 4];
            s += vv.x * tanh_fast(e.x + qv.x);
            s += vv.y * tanh_fast(e.y + qv.y);
            s += vv.z * tanh_fast(e.z + qv.z);
            s += vv.w * tanh_fast(e.w + qv.w);
        }
#pragma unroll
        for (int o = 16; o > 0; o >>= 1) s += __shfl_xor_sync(0xffffffffu, s, o);
        if (lane == 0) sc[l] = s;
    }
    __syncthreads();

    if (w == 0) {
        float sv[4];
        float m = -1e30f;
#pragma unroll
        for (int k = 0; k < 4; k++) { sv[k] = sc[lane * 4 + k]; m = fmaxf(m, sv[k]); }
#pragma unroll
        for (int o = 16; o > 0; o >>= 1) m = fmaxf(m, __shfl_xor_sync(0xffffffffu, m, o));
        float e[4], sum = 0.f;
#pragma unroll
        for (int k = 0; k < 4; k++) { e[k] = __expf(sv[k] - m); sum += e[k]; }
#pragma unroll
        for (int o = 16; o > 0; o >>= 1) sum += __shfl_xor_sync(0xffffffffu, sum, o);
        const float ls  = __logf(sum);
        const float inv = 1.0f / sum;
        float* orow = out + ((size_t)b * L + t) * L;
#pragma unroll
        for (int k = 0; k < 4; k++) {
            orow[lane * 4 + k] = sv[k] - m - ls;
            aj[lane * 4 + k]   = e[k] * inv;
        }
    }
    __syncthreads();

    const int h2 = tid * 2;
    float ax = 0.f, ay = 0.f;
    const float* base = g_enc_out + (size_t)b * L * H + h2;
#pragma unroll 4
    for (int l = 0; l < L; l++) {
        const float a = aj[l];
        const float2 v = *(const float2*)(base + (size_t)l * H);
        ax += a * v.x;
        ay += a * v.y;
    }
    g_ctx[b * H + h2]     = ax;
    g_ctx[b * H + h2 + 1] = ay;
}

}  // namespace

extern "C" void kernel_launch(void* const* d_in, const int* in_sizes, int n_in,
                              void* d_out, int out_size) {
    (void)in_sizes; (void)n_in; (void)out_size;
    const int*   xs      = (const int*)d_in[0];
    const int*   argsort = (const int*)d_in[2];
    const float* enc_Wi  = (const float*)d_in[3];
    const float* enc_Wh  = (const float*)d_in[4];
    const float* enc_b   = (const float*)d_in[5];
    const float* dec_Wi  = (const float*)d_in[6];
    const float* dec_Wh  = (const float*)d_in[7];
    const float* dec_b   = (const float*)d_in[8];
    const float* w1      = (const float*)d_in[9];
    const float* w2      = (const float*)d_in[10];
    const float* vt      = (const float*)d_in[11];
    float* out = (float*)d_out;

    // device-global addresses (host-side symbol queries; no allocation)
    float *p_h, *p_ctx, *p_zpart, *p_qpart, *p_dwcat, *p_dwlast;
    cudaGetSymbolAddress((void**)&p_h,      g_h);
    cudaGetSymbolAddress((void**)&p_ctx,    g_ctx);
    cudaGetSymbolAddress((void**)&p_zpart,  g_zpart);
    cudaGetSymbolAddress((void**)&p_qpart,  g_qpart);
    cudaGetSymbolAddress((void**)&p_dwcat,  g_dwcat);
    cudaGetSymbolAddress((void**)&p_dwlast, g_dwi_last);

    k_init<<<128, 256>>>();
    k_repack<<<256, 256>>>(dec_Wi, dec_Wh);

    const dim3 gates_grid(B * H / 256);               // 512
    const dim3 lstm_gemm(H4 / 64, B / 64, 2);         // (32, 4, 2) = 256 CTAs
    const dim3 q_gemm(H / 64, B / 64, 8);             // (8, 4, 8)  = 256 CTAs

    // ---- encoder: 128 sequential LSTM steps ----
    for (int t = 0; t < L; t++) {
        const float* hp = p_h + (size_t)(t & 1) * (B * H);
        k_gemm<512, 2, false><<<lstm_gemm, 256>>>(enc_Wh, hp, nullptr, p_zpart);
        k_gates<false><<<gates_grid, 256>>>(enc_b, enc_Wi, xs, nullptr, t);
    }

    // ---- hoisted projection enc_w1 = enc_out @ w1^T ----
    k_encw1<<<dim3(H / 64, (B * L) / 64), 256>>>(w1);

    // ---- decoder: 128 sequential steps ----
    for (int t = 0; t < L; t++) {
        const float* hp = p_h + (size_t)(t & 1) * (B * H);
        k_gemm<512, 8, false><<<q_gemm, 256>>>(w2, hp, nullptr, p_qpart);
        k_attn<<<B, 256>>>(vt, out, t);
        k_gemm<1024, 2, true><<<lstm_gemm, 256>>>(p_dwcat, p_ctx, hp, p_zpart);
        k_gates<true><<<gates_grid, 256>>>(dec_b, p_dwlast, xs, argsort, t);
    }
}